// round 14
// baseline (speedup 1.0000x reference)
#include <cuda_runtime.h>

#define Bn 32
#define Tn 2048
#define Fn 2048
#define DQn 1024
#define UNITSn 1024
#define HALFn 1024      // F/2
#define CONCATn 2048    // HALF + DQ
#define SEG 8           // T segments per batch -> grid 256 = single wave
#define TS (Tn / SEG)   // 256 rows per segment block
#define PAIRS 4         // warp pairs per block (8 warps, 256 threads)
#define RPP (TS / PAIRS) // 64 rows per pair
#define NBLK (SEG * Bn) // 256

// Scratch (allocation-free rule: __device__ globals)
__device__ float g_w[CONCATn];               // W1 @ V
__device__ float g_bias;                     // b1·V + bV
__device__ float g_score[Bn * Tn];           // raw scores
__device__ float g_partial[Bn * SEG * Fn];   // per-seg ctx partials (scale e^{m_seg})
__device__ float g_m[Bn * SEG];              // per-segment max
__device__ float g_Z[Bn * SEG];              // per-segment exp-sum at m_seg
__device__ int   g_cnt[Bn];                  // per-batch arrival counter (self-reset)
__device__ int   g_syncw;                    // w-phase arrival counter
__device__ int   g_done;                     // end-of-kernel counter (resets g_syncw)

#define LD8(dst, ptr)                                            \
    do {                                                         \
        _Pragma("unroll")                                        \
        for (int _i = 0; _i < 8; _i++)                           \
            dst[_i] = __ldcs(&(ptr)[lane + 32 * _i]);            \
    } while (0)

// ---------------------------------------------------------------------------
// Single fused kernel: phase-0 cooperative w = W1@V (+bias) OVERLAPPED with
// iteration-0 values prefetch, then warp-pair specialized single-pass
// attention (2 rows per pair barrier), fused combine epilogue.
// ---------------------------------------------------------------------------
__global__ __launch_bounds__(256, 2) void k_all(const float* __restrict__ values,
                                                const float* __restrict__ query,
                                                const float* __restrict__ W1,
                                                const float* __restrict__ V,
                                                const float* __restrict__ b1,
                                                const float* __restrict__ bV,
                                                float* __restrict__ ctx,
                                                float* __restrict__ aw) {
    __shared__ float sw[HALFn];                   // 4 KB: w[:1024]
    __shared__ float s_e0[2][PAIRS], s_e1[2][PAIRS], s_c[2][PAIRS];
    __shared__ float s_m[PAIRS], s_Z[PAIRS];
    __shared__ float swacc[PAIRS * HALFn];        // 16 KB merge buffer
    __shared__ float red[8];
    __shared__ int   s_last;

    int seg = blockIdx.x, b = blockIdx.y;
    int bid = b * SEG + seg;                      // 0..255
    int tid = threadIdx.x, warp = tid >> 5, lane = tid & 31;
    int pair = warp >> 1;
    bool isA = (warp & 1) == 0;
    int barid = 1 + pair;

    int tbase = seg * TS;
    const float* base = values + ((size_t)(b * Tn + tbase)) * Fn;

    // ---- iteration-0 prefetch (independent of g_w) issued FIRST ----
    float4 v0[8], v1[8];
    {
        size_t off = isA ? 0 : HALFn;
        const float4* rp0 = reinterpret_cast<const float4*>(
            base + (size_t)pair * Fn + off);
        const float4* rp1 = reinterpret_cast<const float4*>(
            base + (size_t)(pair + PAIRS) * Fn + off);
        LD8(v0, rp0);
        LD8(v1, rp1);
    }

    // ================= phase 0: cooperative w = W1 @ V =================
    {
        int wc = bid * 8 + warp;                  // 0..2047
        const float4* row = reinterpret_cast<const float4*>(W1 + (size_t)wc * UNITSn);
        const float4* v4  = reinterpret_cast<const float4*>(V);
        float acc = 0.f;
#pragma unroll
        for (int i = 0; i < UNITSn / 128; i++) {
            float4 a = row[lane + i * 32];
            float4 v = v4[lane + i * 32];
            acc += a.x * v.x + a.y * v.y + a.z * v.z + a.w * v.w;
        }
#pragma unroll
        for (int o = 16; o; o >>= 1) acc += __shfl_xor_sync(0xffffffffu, acc, o);
        if (lane == 0) g_w[wc] = acc;

        if (bid == 0 && warp == 0) {              // bias = b1·V + bV
            const float4* b4 = reinterpret_cast<const float4*>(b1);
            float ba = 0.f;
#pragma unroll
            for (int i = 0; i < UNITSn / 128; i++) {
                float4 a = b4[lane + i * 32];
                float4 v = v4[lane + i * 32];
                ba += a.x * v.x + a.y * v.y + a.z * v.z + a.w * v.w;
            }
#pragma unroll
            for (int o = 16; o; o >>= 1) ba += __shfl_xor_sync(0xffffffffu, ba, o);
            if (lane == 0) g_bias = ba + bV[0];
        }
    }
    __threadfence();
    __syncthreads();
    if (tid == 0) {
        atomicAdd(&g_syncw, 1);
        int backoff = 32;
        while (atomicAdd(&g_syncw, 0) < NBLK) {
            __nanosleep(backoff);
            if (backoff < 1024) backoff <<= 1;
        }
    }
    __syncthreads();
    __threadfence();   // acquire: all g_w / g_bias writes visible

    // ================= prologue: sw + qb =================
    for (int i = tid; i < HALFn; i += 256) sw[i] = g_w[i];
    {
        float4 q = reinterpret_cast<const float4*>(query + (size_t)b * DQn)[tid];
        float4 w = reinterpret_cast<const float4*>(g_w + HALFn)[tid];
        float p = q.x * w.x + q.y * w.y + q.z * w.z + q.w * w.w;
#pragma unroll
        for (int o = 16; o; o >>= 1) p += __shfl_xor_sync(0xffffffffu, p, o);
        if (lane == 0) red[warp] = p;
    }
    __syncthreads();
    float qb = g_bias;
#pragma unroll
    for (int i = 0; i < 8; i++) qb += red[i];

    const float4* w4 = reinterpret_cast<const float4*>(sw);

    float4 acc[8];
#pragma unroll
    for (int i = 0; i < 8; i++) acc[i] = make_float4(0.f, 0.f, 0.f, 0.f);
    float m = -1e30f, Z = 0.f;

    // ================= streaming loop: 2 rows per barrier =================
    if (isA) {
#pragma unroll 1
        for (int it = 0; it < RPP / 2; it++) {
            int r0 = (2 * it) * PAIRS + pair;
            if (it != 0) {   // iteration 0 already prefetched
                const float4* rp0 = reinterpret_cast<const float4*>(
                    base + (size_t)r0 * Fn);
                const float4* rp1 = reinterpret_cast<const float4*>(
                    base + (size_t)(r0 + PAIRS) * Fn);
                LD8(v0, rp0);
                LD8(v1, rp1);
            }

            float d0 = 0.f, d1 = 0.f;
#pragma unroll
            for (int i = 0; i < 8; i++) {
                float4 w = w4[lane + 32 * i];
                d0 += v0[i].x * w.x + v0[i].y * w.y + v0[i].z * w.z + v0[i].w * w.w;
                d1 += v1[i].x * w.x + v1[i].y * w.y + v1[i].z * w.z + v1[i].w * w.w;
            }
#pragma unroll
            for (int o = 16; o; o >>= 1) {
                d0 += __shfl_xor_sync(0xffffffffu, d0, o);
                d1 += __shfl_xor_sync(0xffffffffu, d1, o);
            }
            float s0 = d0 + qb;
            float s1 = d1 + qb;

            float smax = fmaxf(s0, s1);
            float c = 1.f;
            if (smax > m) {              // warp-uniform
                c = __expf(m - smax);
                m = smax;
                Z *= c;
            }
            float e0 = __expf(s0 - m);
            float e1 = __expf(s1 - m);
            Z += e0 + e1;
            if (lane == 0) {
                s_e0[it & 1][pair] = e0;
                s_e1[it & 1][pair] = e1;
                s_c[it & 1][pair]  = c;
            }
            asm volatile("bar.sync %0, 64;" :: "r"(barid) : "memory");

            if (lane == 0) {   // off the pre-barrier chain
                __stcs(&g_score[b * Tn + tbase + r0], s0);
                __stcs(&g_score[b * Tn + tbase + r0 + PAIRS], s1);
            }

            if (c != 1.f) {
#pragma unroll
                for (int i = 0; i < 8; i++) {
                    acc[i].x *= c; acc[i].y *= c; acc[i].z *= c; acc[i].w *= c;
                }
            }
#pragma unroll
            for (int i = 0; i < 8; i++) {
                acc[i].x += e0 * v0[i].x + e1 * v1[i].x;
                acc[i].y += e0 * v0[i].y + e1 * v1[i].y;
                acc[i].z += e0 * v0[i].z + e1 * v1[i].z;
                acc[i].w += e0 * v0[i].w + e1 * v1[i].w;
            }
        }
        if (lane == 0) { s_m[pair] = m; s_Z[pair] = Z; }
    } else {
#pragma unroll 1
        for (int it = 0; it < RPP / 2; it++) {
            int r0 = (2 * it) * PAIRS + pair;
            if (it != 0) {   // iteration 0 already prefetched
                const float4* rp0 = reinterpret_cast<const float4*>(
                    base + (size_t)r0 * Fn + HALFn);
                const float4* rp1 = reinterpret_cast<const float4*>(
                    base + (size_t)(r0 + PAIRS) * Fn + HALFn);
                LD8(v0, rp0);
                LD8(v1, rp1);
            }
            asm volatile("bar.sync %0, 64;" :: "r"(barid) : "memory");
            float e0 = s_e0[it & 1][pair];
            float e1 = s_e1[it & 1][pair];
            float c  = s_c[it & 1][pair];
            if (c != 1.f) {
#pragma unroll
                for (int i = 0; i < 8; i++) {
                    acc[i].x *= c; acc[i].y *= c; acc[i].z *= c; acc[i].w *= c;
                }
            }
#pragma unroll
            for (int i = 0; i < 8; i++) {
                acc[i].x += e0 * v0[i].x + e1 * v1[i].x;
                acc[i].y += e0 * v0[i].y + e1 * v1[i].y;
                acc[i].z += e0 * v0[i].z + e1 * v1[i].z;
                acc[i].w += e0 * v0[i].w + e1 * v1[i].w;
            }
        }
    }
    __syncthreads();

    // ---- merge 4 pairs into segment partial ----
    float mseg = s_m[0];
#pragma unroll
    for (int p = 1; p < PAIRS; p++) mseg = fmaxf(mseg, s_m[p]);
    float wt[PAIRS];
    float Zseg = 0.f;
#pragma unroll
    for (int p = 0; p < PAIRS; p++) {
        wt[p] = __expf(s_m[p] - mseg);
        Zseg += s_Z[p] * wt[p];
    }

    float* part = g_partial + ((size_t)(b * SEG + seg)) * Fn;

    if (isA) {
#pragma unroll
        for (int i = 0; i < 8; i++)
            *reinterpret_cast<float4*>(&swacc[pair * HALFn + 4 * (lane + 32 * i)]) = acc[i];
    }
    __syncthreads();
    {
        float4 r = make_float4(0.f, 0.f, 0.f, 0.f);
#pragma unroll
        for (int p = 0; p < PAIRS; p++) {
            float4 c = *reinterpret_cast<const float4*>(&swacc[p * HALFn + 4 * tid]);
            r.x += wt[p] * c.x; r.y += wt[p] * c.y;
            r.z += wt[p] * c.z; r.w += wt[p] * c.w;
        }
        __stcs(reinterpret_cast<float4*>(&part[4 * tid]), r);
    }
    __syncthreads();
    if (!isA) {
#pragma unroll
        for (int i = 0; i < 8; i++)
            *reinterpret_cast<float4*>(&swacc[pair * HALFn + 4 * (lane + 32 * i)]) = acc[i];
    }
    __syncthreads();
    {
        float4 r = make_float4(0.f, 0.f, 0.f, 0.f);
#pragma unroll
        for (int p = 0; p < PAIRS; p++) {
            float4 c = *reinterpret_cast<const float4*>(&swacc[p * HALFn + 4 * tid]);
            r.x += wt[p] * c.x; r.y += wt[p] * c.y;
            r.z += wt[p] * c.z; r.w += wt[p] * c.w;
        }
        __stcs(reinterpret_cast<float4*>(&part[HALFn + 4 * tid]), r);
    }

    if (tid == 0) {
        g_m[b * SEG + seg] = mseg;
        g_Z[b * SEG + seg] = Zseg;
    }

    // ---- fused epilogue: last-arriving block per batch combines ----
    __threadfence();
    __syncthreads();
    if (tid == 0) {
        int prev = atomicAdd(&g_cnt[b], 1);
        s_last = (prev == SEG - 1);
    }
    __syncthreads();
    if (s_last) {
        __threadfence();   // acquire side: partials/scores from peer blocks

        float gm = -1e30f;
#pragma unroll
        for (int s = 0; s < SEG; s++) gm = fmaxf(gm, g_m[b * SEG + s]);
        float Zg = 0.f;
#pragma unroll
        for (int s = 0; s < SEG; s++) Zg += g_Z[b * SEG + s] * __expf(g_m[b * SEG + s] - gm);
        float inv = 1.0f / Zg;

        float4 c0 = make_float4(0.f, 0.f, 0.f, 0.f);
        float4 c1 = make_float4(0.f, 0.f, 0.f, 0.f);
#pragma unroll
        for (int s = 0; s < SEG; s++) {
            float w = __expf(g_m[b * SEG + s] - gm) * inv;
            const float* ps = g_partial + ((size_t)(b * SEG + s)) * Fn;
            float4 p0 = *reinterpret_cast<const float4*>(&ps[4 * tid]);
            float4 p1 = *reinterpret_cast<const float4*>(&ps[HALFn + 4 * tid]);
            c0.x += w * p0.x; c0.y += w * p0.y; c0.z += w * p0.z; c0.w += w * p0.w;
            c1.x += w * p1.x; c1.y += w * p1.y; c1.z += w * p1.z; c1.w += w * p1.w;
        }
        *reinterpret_cast<float4*>(&ctx[(size_t)b * Fn + 4 * tid]) = c0;
        *reinterpret_cast<float4*>(&ctx[(size_t)b * Fn + HALFn + 4 * tid]) = c1;

#pragma unroll
        for (int h = 0; h < 2; h++) {
            int off = h * 1024 + 4 * tid;
            float4 sc = *reinterpret_cast<const float4*>(&g_score[b * Tn + off]);
            float4 r;
            r.x = __expf(sc.x - gm) * inv;
            r.y = __expf(sc.y - gm) * inv;
            r.z = __expf(sc.z - gm) * inv;
            r.w = __expf(sc.w - gm) * inv;
            *reinterpret_cast<float4*>(&aw[b * Tn + off]) = r;
        }

        if (tid == 0) g_cnt[b] = 0;   // reset for next graph replay
    }

    // ---- end-of-kernel reset of the w-phase counter (replay safety) ----
    if (tid == 0) {
        int d = atomicAdd(&g_done, 1);
        if (d == NBLK - 1) {
            g_syncw = 0;
            __threadfence();
            g_done = 0;
        }
    }
}

// ---------------------------------------------------------------------------
extern "C" void kernel_launch(void* const* d_in, const int* in_sizes, int n_in,
                              void* d_out, int out_size) {
    const float* query  = (const float*)d_in[0];
    const float* values = (const float*)d_in[1];
    const float* W1     = (const float*)d_in[2];
    const float* b1     = (const float*)d_in[3];
    const float* V      = (const float*)d_in[4];
    const float* bV     = (const float*)d_in[5];

    float* out = (float*)d_out;
    float* ctx = out;                 // [B, F]   context_vector (32,1,2048)
    float* aw  = out + Bn * Fn;       // [B, T]   attention_weights (32,2048,1)

    dim3 g(SEG, Bn);
    k_all<<<g, 256>>>(values, query, W1, V, b1, bV, ctx, aw);
}

// round 15
// speedup vs baseline: 1.0667x; 1.0667x over previous
#include <cuda_runtime.h>

#define Bn 32
#define Tn 2048
#define Fn 2048
#define DQn 1024
#define UNITSn 1024
#define HALFn 1024      // F/2
#define CONCATn 2048    // HALF + DQ
#define SEG 8           // T segments per batch -> grid 256 = single wave
#define TS (Tn / SEG)   // 256 rows per segment block
#define PAIRS 4         // warp pairs per block (8 warps, 256 threads)
#define RPP (TS / PAIRS) // 64 rows per pair
#define NBLK (SEG * Bn) // 256

// Scratch (allocation-free rule: __device__ globals)
__device__ float g_w[CONCATn];               // W1 @ V
__device__ float g_bias;                     // b1·V + bV
__device__ float g_score[Bn * Tn];           // raw scores
__device__ float g_partial[Bn * SEG * Fn];   // per-seg ctx partials (scale e^{m_seg})
__device__ float g_m[Bn * SEG];              // per-segment max
__device__ float g_Z[Bn * SEG];              // per-segment exp-sum at m_seg
__device__ int   g_cnt[Bn];                  // per-batch arrival counter (self-reset)
__device__ int   g_syncw;                    // w-phase arrival counter
__device__ int   g_done;                     // end-of-kernel counter (resets g_syncw)

#define LD8(dst, ptr)                                            \
    do {                                                         \
        _Pragma("unroll")                                        \
        for (int _i = 0; _i < 8; _i++)                           \
            dst[_i] = __ldcs(&(ptr)[lane + 32 * _i]);            \
    } while (0)

// ---------------------------------------------------------------------------
// Single fused kernel (R13 structure): phase-0 cooperative w = W1@V (+bias),
// then warp-pair specialized single-pass attention processing TWO rows per
// pair-barrier, fused combine epilogue. Scores stored after the barrier
// (off A's pre-barrier critical chain).
// ---------------------------------------------------------------------------
__global__ __launch_bounds__(256, 2) void k_all(const float* __restrict__ values,
                                                const float* __restrict__ query,
                                                const float* __restrict__ W1,
                                                const float* __restrict__ V,
                                                const float* __restrict__ b1,
                                                const float* __restrict__ bV,
                                                float* __restrict__ ctx,
                                                float* __restrict__ aw) {
    __shared__ float sw[HALFn];                   // 4 KB: w[:1024]
    __shared__ float s_e0[2][PAIRS], s_e1[2][PAIRS], s_c[2][PAIRS];
    __shared__ float s_m[PAIRS], s_Z[PAIRS];
    __shared__ float swacc[PAIRS * HALFn];        // 16 KB merge buffer
    __shared__ float red[8];
    __shared__ int   s_last;

    int seg = blockIdx.x, b = blockIdx.y;
    int bid = b * SEG + seg;                      // 0..255
    int tid = threadIdx.x, warp = tid >> 5, lane = tid & 31;
    int pair = warp >> 1;
    bool isA = (warp & 1) == 0;
    int barid = 1 + pair;

    // ================= phase 0: cooperative w = W1 @ V =================
    {
        int wc = bid * 8 + warp;                  // 0..2047
        const float4* row = reinterpret_cast<const float4*>(W1 + (size_t)wc * UNITSn);
        const float4* v4  = reinterpret_cast<const float4*>(V);
        float acc = 0.f;
#pragma unroll
        for (int i = 0; i < UNITSn / 128; i++) {
            float4 a = row[lane + i * 32];
            float4 v = v4[lane + i * 32];
            acc += a.x * v.x + a.y * v.y + a.z * v.z + a.w * v.w;
        }
#pragma unroll
        for (int o = 16; o; o >>= 1) acc += __shfl_xor_sync(0xffffffffu, acc, o);
        if (lane == 0) g_w[wc] = acc;

        if (bid == 0 && warp == 0) {              // bias = b1·V + bV
            const float4* b4 = reinterpret_cast<const float4*>(b1);
            float ba = 0.f;
#pragma unroll
            for (int i = 0; i < UNITSn / 128; i++) {
                float4 a = b4[lane + i * 32];
                float4 v = v4[lane + i * 32];
                ba += a.x * v.x + a.y * v.y + a.z * v.z + a.w * v.w;
            }
#pragma unroll
            for (int o = 16; o; o >>= 1) ba += __shfl_xor_sync(0xffffffffu, ba, o);
            if (lane == 0) g_bias = ba + bV[0];
        }
    }
    __threadfence();
    __syncthreads();
    if (tid == 0) {
        atomicAdd(&g_syncw, 1);
        int backoff = 32;
        while (atomicAdd(&g_syncw, 0) < NBLK) {
            __nanosleep(backoff);
            if (backoff < 1024) backoff <<= 1;
        }
    }
    __syncthreads();
    __threadfence();   // acquire: all g_w / g_bias writes visible

    // ================= prologue: sw + qb =================
    for (int i = tid; i < HALFn; i += 256) sw[i] = g_w[i];
    {
        float4 q = reinterpret_cast<const float4*>(query + (size_t)b * DQn)[tid];
        float4 w = reinterpret_cast<const float4*>(g_w + HALFn)[tid];
        float p = q.x * w.x + q.y * w.y + q.z * w.z + q.w * w.w;
#pragma unroll
        for (int o = 16; o; o >>= 1) p += __shfl_xor_sync(0xffffffffu, p, o);
        if (lane == 0) red[warp] = p;
    }
    __syncthreads();
    float qb = g_bias;
#pragma unroll
    for (int i = 0; i < 8; i++) qb += red[i];

    int tbase = seg * TS;
    const float* base = values + ((size_t)(b * Tn + tbase)) * Fn;
    const float4* w4 = reinterpret_cast<const float4*>(sw);

    float4 acc[8];
#pragma unroll
    for (int i = 0; i < 8; i++) acc[i] = make_float4(0.f, 0.f, 0.f, 0.f);
    float m = -1e30f, Z = 0.f;

    // ================= streaming loop: 2 rows per barrier =================
    if (isA) {
#pragma unroll 1
        for (int it = 0; it < RPP / 2; it++) {
            int r0 = (2 * it) * PAIRS + pair;
            const float4* rp0 = reinterpret_cast<const float4*>(base + (size_t)r0 * Fn);
            const float4* rp1 = reinterpret_cast<const float4*>(
                base + (size_t)(r0 + PAIRS) * Fn);
            float4 v0[8], v1[8];
            LD8(v0, rp0);
            LD8(v1, rp1);

            float d0 = 0.f, d1 = 0.f;
#pragma unroll
            for (int i = 0; i < 8; i++) {
                float4 w = w4[lane + 32 * i];
                d0 += v0[i].x * w.x + v0[i].y * w.y + v0[i].z * w.z + v0[i].w * w.w;
                d1 += v1[i].x * w.x + v1[i].y * w.y + v1[i].z * w.z + v1[i].w * w.w;
            }
#pragma unroll
            for (int o = 16; o; o >>= 1) {
                d0 += __shfl_xor_sync(0xffffffffu, d0, o);
                d1 += __shfl_xor_sync(0xffffffffu, d1, o);
            }
            float s0 = d0 + qb;
            float s1 = d1 + qb;

            float smax = fmaxf(s0, s1);
            float c = 1.f;
            if (smax > m) {              // warp-uniform
                c = __expf(m - smax);
                m = smax;
                Z *= c;
            }
            float e0 = __expf(s0 - m);
            float e1 = __expf(s1 - m);
            Z += e0 + e1;
            if (lane == 0) {
                s_e0[it & 1][pair] = e0;
                s_e1[it & 1][pair] = e1;
                s_c[it & 1][pair]  = c;
            }
            asm volatile("bar.sync %0, 64;" :: "r"(barid) : "memory");

            if (lane == 0) {   // after the barrier: off the critical chain
                __stcs(&g_score[b * Tn + tbase + r0], s0);
                __stcs(&g_score[b * Tn + tbase + r0 + PAIRS], s1);
            }

            if (c != 1.f) {
#pragma unroll
                for (int i = 0; i < 8; i++) {
                    acc[i].x *= c; acc[i].y *= c; acc[i].z *= c; acc[i].w *= c;
                }
            }
#pragma unroll
            for (int i = 0; i < 8; i++) {
                acc[i].x += e0 * v0[i].x + e1 * v1[i].x;
                acc[i].y += e0 * v0[i].y + e1 * v1[i].y;
                acc[i].z += e0 * v0[i].z + e1 * v1[i].z;
                acc[i].w += e0 * v0[i].w + e1 * v1[i].w;
            }
        }
        if (lane == 0) { s_m[pair] = m; s_Z[pair] = Z; }
    } else {
#pragma unroll 1
        for (int it = 0; it < RPP / 2; it++) {
            int r0 = (2 * it) * PAIRS + pair;
            const float4* rp0 = reinterpret_cast<const float4*>(
                base + (size_t)r0 * Fn + HALFn);
            const float4* rp1 = reinterpret_cast<const float4*>(
                base + (size_t)(r0 + PAIRS) * Fn + HALFn);
            float4 v0[8], v1[8];
            LD8(v0, rp0);
            LD8(v1, rp1);
            asm volatile("bar.sync %0, 64;" :: "r"(barid) : "memory");
            float e0 = s_e0[it & 1][pair];
            float e1 = s_e1[it & 1][pair];
            float c  = s_c[it & 1][pair];
            if (c != 1.f) {
#pragma unroll
                for (int i = 0; i < 8; i++) {
                    acc[i].x *= c; acc[i].y *= c; acc[i].z *= c; acc[i].w *= c;
                }
            }
#pragma unroll
            for (int i = 0; i < 8; i++) {
                acc[i].x += e0 * v0[i].x + e1 * v1[i].x;
                acc[i].y += e0 * v0[i].y + e1 * v1[i].y;
                acc[i].z += e0 * v0[i].z + e1 * v1[i].z;
                acc[i].w += e0 * v0[i].w + e1 * v1[i].w;
            }
        }
    }
    __syncthreads();

    // ---- merge 4 pairs into segment partial ----
    float mseg = s_m[0];
#pragma unroll
    for (int p = 1; p < PAIRS; p++) mseg = fmaxf(mseg, s_m[p]);
    float wt[PAIRS];
    float Zseg = 0.f;
#pragma unroll
    for (int p = 0; p < PAIRS; p++) {
        wt[p] = __expf(s_m[p] - mseg);
        Zseg += s_Z[p] * wt[p];
    }

    float* part = g_partial + ((size_t)(b * SEG + seg)) * Fn;

    if (isA) {
#pragma unroll
        for (int i = 0; i < 8; i++)
            *reinterpret_cast<float4*>(&swacc[pair * HALFn + 4 * (lane + 32 * i)]) = acc[i];
    }
    __syncthreads();
    {
        float4 r = make_float4(0.f, 0.f, 0.f, 0.f);
#pragma unroll
        for (int p = 0; p < PAIRS; p++) {
            float4 c = *reinterpret_cast<const float4*>(&swacc[p * HALFn + 4 * tid]);
            r.x += wt[p] * c.x; r.y += wt[p] * c.y;
            r.z += wt[p] * c.z; r.w += wt[p] * c.w;
        }
        __stcs(reinterpret_cast<float4*>(&part[4 * tid]), r);
    }
    __syncthreads();
    if (!isA) {
#pragma unroll
        for (int i = 0; i < 8; i++)
            *reinterpret_cast<float4*>(&swacc[pair * HALFn + 4 * (lane + 32 * i)]) = acc[i];
    }
    __syncthreads();
    {
        float4 r = make_float4(0.f, 0.f, 0.f, 0.f);
#pragma unroll
        for (int p = 0; p < PAIRS; p++) {
            float4 c = *reinterpret_cast<const float4*>(&swacc[p * HALFn + 4 * tid]);
            r.x += wt[p] * c.x; r.y += wt[p] * c.y;
            r.z += wt[p] * c.z; r.w += wt[p] * c.w;
        }
        __stcs(reinterpret_cast<float4*>(&part[HALFn + 4 * tid]), r);
    }

    if (tid == 0) {
        g_m[b * SEG + seg] = mseg;
        g_Z[b * SEG + seg] = Zseg;
    }

    // ---- fused epilogue: last-arriving block per batch combines ----
    __threadfence();
    __syncthreads();
    if (tid == 0) {
        int prev = atomicAdd(&g_cnt[b], 1);
        s_last = (prev == SEG - 1);
    }
    __syncthreads();
    if (s_last) {
        __threadfence();   // acquire side: partials/scores from peer blocks

        float gm = -1e30f;
#pragma unroll
        for (int s = 0; s < SEG; s++) gm = fmaxf(gm, g_m[b * SEG + s]);
        float Zg = 0.f;
#pragma unroll
        for (int s = 0; s < SEG; s++) Zg += g_Z[b * SEG + s] * __expf(g_m[b * SEG + s] - gm);
        float inv = 1.0f / Zg;

        float4 c0 = make_float4(0.f, 0.f, 0.f, 0.f);
        float4 c1 = make_float4(0.f, 0.f, 0.f, 0.f);
#pragma unroll
        for (int s = 0; s < SEG; s++) {
            float w = __expf(g_m[b * SEG + s] - gm) * inv;
            const float* ps = g_partial + ((size_t)(b * SEG + s)) * Fn;
            float4 p0 = *reinterpret_cast<const float4*>(&ps[4 * tid]);
            float4 p1 = *reinterpret_cast<const float4*>(&ps[HALFn + 4 * tid]);
            c0.x += w * p0.x; c0.y += w * p0.y; c0.z += w * p0.z; c0.w += w * p0.w;
            c1.x += w * p1.x; c1.y += w * p1.y; c1.z += w * p1.z; c1.w += w * p1.w;
        }
        *reinterpret_cast<float4*>(&ctx[(size_t)b * Fn + 4 * tid]) = c0;
        *reinterpret_cast<float4*>(&ctx[(size_t)b * Fn + HALFn + 4 * tid]) = c1;

#pragma unroll
        for (int h = 0; h < 2; h++) {
            int off = h * 1024 + 4 * tid;
            float4 sc = *reinterpret_cast<const float4*>(&g_score[b * Tn + off]);
            float4 r;
            r.x = __expf(sc.x - gm) * inv;
            r.y = __expf(sc.y - gm) * inv;
            r.z = __expf(sc.z - gm) * inv;
            r.w = __expf(sc.w - gm) * inv;
            *reinterpret_cast<float4*>(&aw[b * Tn + off]) = r;
        }

        if (tid == 0) g_cnt[b] = 0;   // reset for next graph replay
    }

    // ---- end-of-kernel reset of the w-phase counter (replay safety) ----
    if (tid == 0) {
        int d = atomicAdd(&g_done, 1);
        if (d == NBLK - 1) {
            g_syncw = 0;
            __threadfence();
            g_done = 0;
        }
    }
}

// ---------------------------------------------------------------------------
extern "C" void kernel_launch(void* const* d_in, const int* in_sizes, int n_in,
                              void* d_out, int out_size) {
    const float* query  = (const float*)d_in[0];
    const float* values = (const float*)d_in[1];
    const float* W1     = (const float*)d_in[2];
    const float* b1     = (const float*)d_in[3];
    const float* V      = (const float*)d_in[4];
    const float* bV     = (const float*)d_in[5];

    float* out = (float*)d_out;
    float* ctx = out;                 // [B, F]   context_vector (32,1,2048)
    float* aw  = out + Bn * Fn;       // [B, T]   attention_weights (32,2048,1)

    dim3 g(SEG, Bn);
    k_all<<<g, 256>>>(values, query, W1, V, b1, bV, ctx, aw);
}